// round 9
// baseline (speedup 1.0000x reference)
#include <cuda_runtime.h>
#include <cuda_pipeline_primitives.h>

// Problem constants (fixed by the reference):
//   image 1000x1000, patch 5x5 -> 200x200 = 40000 patches
//   coefficients [40000, 3, 10, 2], bias [40000, 3]
//   out [3, 1000000]
#define IMG_W           1000
#define NUM_PIX         1000000
#define PATCH           5
#define PATCHES_PER_ROW 200
#define COEF_PER_PATCH  60          // 3*10*2
#define PB              25          // patches per block (one eighth of a patch-row)
#define NTHREADS        128         // 125 compute threads (97.6% active)
#define GRID            1600        // 200 patch-rows x 8 blocks

// Packed dual-FP32 FMA (Blackwell)
__device__ __forceinline__ unsigned long long ffma2(unsigned long long a,
                                                    unsigned long long b,
                                                    unsigned long long c)
{
    unsigned long long d;
    asm("fma.rn.f32x2 %0, %1, %2, %3;" : "=l"(d) : "l"(a), "l"(b), "l"(c));
    return d;
}
__device__ __forceinline__ unsigned long long as_u64(double v)
{
    return __double_as_longlong(v);
}
__device__ __forceinline__ float hsum2(unsigned long long v)
{
    float lo, hi;
    asm("mov.b64 {%0, %1}, %2;" : "=f"(lo), "=f"(hi) : "l"(v));
    return lo + hi;
}

__global__ __launch_bounds__(NTHREADS, 12)
void ts_kernel(const float* __restrict__ pix,
               const float* __restrict__ coef,
               const float* __restrict__ bias,
               float* __restrict__ out)
{
    __shared__ float sc[PB * COEF_PER_PATCH];   // 1500 floats, LINEAR (6000 B)
    __shared__ float sb[PB * 3 + 1];            // bias, 75 used

    const int tid = threadIdx.x;
    const int b   = blockIdx.x;          // 0..1599
    const int pr  = b >> 3;              // patch row 0..199
    const int cb  = (b & 7) * PB;        // patch-col base: 0,25,...,175
    const int pbase   = pr * PATCHES_PER_ROW + cb;
    const int colBase = cb * PATCH;      // pixel column base

    // ---- Coefficient + bias staging (cp.async; coeffs 16B, bias 4B granules) ----
    {
        // 25 patches * 15 float4 = 375 float4, contiguous (pbase*240B is 16B-aligned).
        const float4* g4 = (const float4*)(coef + (size_t)pbase * COEF_PER_PATCH);
        #pragma unroll
        for (int k = 0; k < 3; k++) {
            int idx = tid + k * NTHREADS;
            if (idx < 375)
                __pipeline_memcpy_async(&sc[idx * 4], &g4[idx], 16);
        }
        // Bias: 75 floats; pbase*3*4B not 16B-aligned for PB=25 -> 4B copies.
        if (tid < PB * 3)
            __pipeline_memcpy_async(&sb[tid], bias + (size_t)pbase * 3 + tid, 4);
        __pipeline_commit();
    }

    // ---- Early pixel loads (independent of smem; overlap the coeff wait) ----
    const int p_local = tid % PB;        // 0..24
    const int seg     = tid / PB;        // 0..5 (only 0..4 compute)
    const int pixBase = (pr * PATCH + seg) * IMG_W + colBase + p_local * PATCH;

    unsigned long long xy[PATCH];
    if (tid < PB * PATCH) {
        const double* pp8 = (const double*)pix + pixBase;   // pixel n = double n
        #pragma unroll
        for (int i = 0; i < PATCH; i++)
            xy[i] = as_u64(pp8[i]);
    }

    __pipeline_wait_prior(0);
    __syncthreads();

    // ---- Compute + direct stores (125 threads; thread = 5-pixel segment) ----
    if (tid < PB * PATCH) {
        const float* cc0 = &sc[p_local * COEF_PER_PATCH];   // 240B stride: conflict-free LDS.128
        const float bv0 = sb[p_local * 3 + 0];
        const float bv1 = sb[p_local * 3 + 1];
        const float bv2 = sb[p_local * 3 + 2];
        float* o = out + pixBase;

        #pragma unroll
        for (int ch = 0; ch < 3; ch++) {
            const double2* cp = (const double2*)(cc0 + ch * 20);  // 16B-aligned
            const float bv = (ch == 0) ? bv0 : (ch == 1) ? bv1 : bv2;

            unsigned long long acc[PATCH];
            {
                double2 v = cp[4];                       // pairs t=8, t=9
                const unsigned long long c8 = as_u64(v.x), c9 = as_u64(v.y);
                #pragma unroll
                for (int i = 0; i < PATCH; i++)
                    acc[i] = ffma2(c9, xy[i], c8);
            }
            #pragma unroll
            for (int j = 3; j >= 0; j--) {
                double2 v = cp[j];                       // pairs t=2j, t=2j+1
                const unsigned long long clo = as_u64(v.x), chi = as_u64(v.y);
                #pragma unroll
                for (int i = 0; i < PATCH; i++)
                    acc[i] = ffma2(acc[i], xy[i], chi);
                #pragma unroll
                for (int i = 0; i < PATCH; i++)
                    acc[i] = ffma2(acc[i], xy[i], clo);
            }
            float* oc = o + ch * NUM_PIX;
            #pragma unroll
            for (int i = 0; i < PATCH; i++)
                oc[i] = hsum2(acc[i]) + bv;              // warp run: contiguous stores
        }
    }
}

extern "C" void kernel_launch(void* const* d_in, const int* in_sizes, int n_in,
                              void* d_out, int out_size)
{
    const float* pix  = (const float*)d_in[0];   // [1000000, 2]
    const float* coef = (const float*)d_in[1];   // [40000, 3, 10, 2]
    const float* bias = (const float*)d_in[2];   // [40000, 3]
    float* out = (float*)d_out;                  // [3, 1000000]

    (void)in_sizes; (void)n_in; (void)out_size;
    ts_kernel<<<GRID, NTHREADS>>>(pix, coef, bias, out);
}

// round 10
// speedup vs baseline: 1.0438x; 1.0438x over previous
#include <cuda_runtime.h>
#include <cstdint>

// Problem constants (fixed by the reference):
//   image 1000x1000, patch 5x5 -> 200x200 = 40000 patches
//   coefficients [40000, 3, 10, 2], bias [40000, 3]
//   out [3, 1000000]
#define IMG_W           1000
#define NUM_PIX         1000000
#define PATCH           5
#define PATCHES_PER_ROW 200
#define COEF_PER_PATCH  60          // 3*10*2
#define PB              40          // patches per tile
#define NTHREADS        256
#define GRID            888         // 148 SMs x 6 CTAs: exactly one wave
#define NDUAL           112         // blocks 0..111 also handle tile 888+b
#define BUF_F           2528        // floats per stage: 2400 coeff + 128 bias area
#define SB_OFF          2400

// Packed dual-FP32 FMA (Blackwell)
__device__ __forceinline__ unsigned long long ffma2(unsigned long long a,
                                                    unsigned long long b,
                                                    unsigned long long c)
{
    unsigned long long d;
    asm("fma.rn.f32x2 %0, %1, %2, %3;" : "=l"(d) : "l"(a), "l"(b), "l"(c));
    return d;
}
__device__ __forceinline__ unsigned long long as_u64(double v)
{
    return __double_as_longlong(v);
}
__device__ __forceinline__ float hsum2(unsigned long long v)
{
    float lo, hi;
    asm("mov.b64 {%0, %1}, %2;" : "=f"(lo), "=f"(hi) : "l"(v));
    return lo + hi;
}
__device__ __forceinline__ uint32_t s2u(const void* p)
{
    return (uint32_t)__cvta_generic_to_shared(p);
}

// One thread issues the whole tile's staging: 2 bulk copies -> mbarrier.
__device__ __forceinline__ void issue_tile_copy(int tile, float* buf,
                                                unsigned long long* mb,
                                                const float* __restrict__ coef,
                                                const float* __restrict__ bias)
{
    const int pr = tile / 5;
    const int cb = (tile - pr * 5) * PB;
    const size_t pbase = (size_t)pr * PATCHES_PER_ROW + cb;
    const uint32_t m = s2u(mb);
    asm volatile("mbarrier.arrive.expect_tx.shared.b64 _, [%0], %1;"
                 :: "r"(m), "r"(10080u) : "memory");
    // Coefficients: 40*240 = 9600 B, 16B-aligned both sides.
    asm volatile("cp.async.bulk.shared::cta.global.mbarrier::complete_tx::bytes "
                 "[%0], [%1], %2, [%3];"
                 :: "r"(s2u(buf)), "l"(coef + pbase * COEF_PER_PATCH),
                    "r"(9600u), "r"(m) : "memory");
    // Bias: 480 B (pbase multiple of 40 -> byte offset multiple of 480, 16B-aligned).
    asm volatile("cp.async.bulk.shared::cta.global.mbarrier::complete_tx::bytes "
                 "[%0], [%1], %2, [%3];"
                 :: "r"(s2u(buf + SB_OFF)), "l"(bias + pbase * 3),
                    "r"(480u), "r"(m) : "memory");
}

__device__ __forceinline__ void mbar_wait(unsigned long long* mb)
{
    const uint32_t m = s2u(mb);
    asm volatile(
        "{\n\t"
        ".reg .pred P;\n"
        "W%=:\n\t"
        "mbarrier.try_wait.parity.shared.b64 P, [%0], 0;\n\t"
        "@!P bra W%=;\n\t"
        "}" :: "r"(m) : "memory");
}

// Compute + direct stores for one tile (caller guarantees tid < 200).
__device__ __forceinline__ void compute_store(const float* buf,
                                              const unsigned long long* xy,
                                              int pixBase, int p_local,
                                              float* __restrict__ out)
{
    const float* cc0 = &buf[p_local * COEF_PER_PATCH];   // 240B stride: conflict-free LDS.128
    float* o = out + pixBase;

    #pragma unroll
    for (int ch = 0; ch < 3; ch++) {
        const double2* cp = (const double2*)(cc0 + ch * 20);  // 16B-aligned
        const float bv = buf[SB_OFF + p_local * 3 + ch];

        unsigned long long acc[PATCH];
        {
            double2 v = cp[4];                       // pairs t=8, t=9
            const unsigned long long c8 = as_u64(v.x), c9 = as_u64(v.y);
            #pragma unroll
            for (int i = 0; i < PATCH; i++)
                acc[i] = ffma2(c9, xy[i], c8);
        }
        #pragma unroll
        for (int j = 3; j >= 0; j--) {
            double2 v = cp[j];                       // pairs t=2j, t=2j+1
            const unsigned long long clo = as_u64(v.x), chi = as_u64(v.y);
            #pragma unroll
            for (int i = 0; i < PATCH; i++)
                acc[i] = ffma2(acc[i], xy[i], chi);
            #pragma unroll
            for (int i = 0; i < PATCH; i++)
                acc[i] = ffma2(acc[i], xy[i], clo);
        }
        float* oc = o + ch * NUM_PIX;
        #pragma unroll
        for (int i = 0; i < PATCH; i++)
            oc[i] = hsum2(acc[i]) + bv;              // warp run: contiguous 640B
    }
}

__global__ __launch_bounds__(NTHREADS, 6)
void ts_kernel(const float* __restrict__ pix,
               const float* __restrict__ coef,
               const float* __restrict__ bias,
               float* __restrict__ out)
{
    __shared__ __align__(16) float sc[2][BUF_F];     // 2 stages: ~20.2 KB
    __shared__ unsigned long long mbar[2];

    const int tid  = threadIdx.x;
    const int b    = blockIdx.x;          // 0..887
    const bool dual = (b < NDUAL);
    const int tile1 = b + GRID;

    if (tid == 0) {
        asm volatile("mbarrier.init.shared.b64 [%0], %1;"
                     :: "r"(s2u(&mbar[0])), "r"(1) : "memory");
        asm volatile("mbarrier.init.shared.b64 [%0], %1;"
                     :: "r"(s2u(&mbar[1])), "r"(1) : "memory");
    }
    __syncthreads();                      // mbarrier init visible

    if (tid == 0) {
        issue_tile_copy(b, &sc[0][0], &mbar[0], coef, bias);
        if (dual) issue_tile_copy(tile1, &sc[1][0], &mbar[1], coef, bias);
    }

    const int p_local = tid % PB;        // 0..39
    const int seg     = tid / PB;        // 0..6 (only 0..4 compute)
    const bool active = (tid < PB * PATCH);

    // ---- Tile 0: pixel LDGs overlap the TMA wait ----
    {
        const int pr0      = b / 5;
        const int colBase0 = (b - pr0 * 5) * PB * PATCH;
        const int pixBase0 = (pr0 * PATCH + seg) * IMG_W + colBase0 + p_local * PATCH;

        unsigned long long xy[PATCH];
        if (active) {
            const double* pp8 = (const double*)pix + pixBase0;
            #pragma unroll
            for (int i = 0; i < PATCH; i++)
                xy[i] = as_u64(pp8[i]);
        }
        mbar_wait(&mbar[0]);
        if (active)
            compute_store(&sc[0][0], xy, pixBase0, p_local, out);
    }

    // ---- Tile 1 (dual blocks only; TMA has been in flight the whole time) ----
    if (dual) {
        const int pr1      = tile1 / 5;
        const int colBase1 = (tile1 - pr1 * 5) * PB * PATCH;
        const int pixBase1 = (pr1 * PATCH + seg) * IMG_W + colBase1 + p_local * PATCH;

        unsigned long long xy[PATCH];
        if (active) {
            const double* pp8 = (const double*)pix + pixBase1;
            #pragma unroll
            for (int i = 0; i < PATCH; i++)
                xy[i] = as_u64(pp8[i]);
        }
        mbar_wait(&mbar[1]);
        if (active)
            compute_store(&sc[1][0], xy, pixBase1, p_local, out);
    }
}

extern "C" void kernel_launch(void* const* d_in, const int* in_sizes, int n_in,
                              void* d_out, int out_size)
{
    const float* pix  = (const float*)d_in[0];   // [1000000, 2]
    const float* coef = (const float*)d_in[1];   // [40000, 3, 10, 2]
    const float* bias = (const float*)d_in[2];   // [40000, 3]
    float* out = (float*)d_out;                  // [3, 1000000]

    (void)in_sizes; (void)n_in; (void)out_size;
    ts_kernel<<<GRID, NTHREADS>>>(pix, coef, bias, out);
}